// round 2
// baseline (speedup 1.0000x reference)
#include <cuda_runtime.h>
#include <stdint.h>

// ---------------------------------------------------------------------------
// Static index tables for the valid (i, ph) combos (same table serves (j, pw)).
// Valid means i2 = i + 2*ph - 14 in [0,7). 25 combos per axis -> 625 features.
// Ordered i-major, then ph ascending.
// ---------------------------------------------------------------------------
__constant__ int c_I [25] = {0,0,0,0, 1,1,1, 2,2,2,2, 3,3,3, 4,4,4,4, 5,5,5, 6,6,6,6};
__constant__ int c_PH[25] = {7,8,9,10, 7,8,9, 6,7,8,9, 6,7,8, 5,6,7,8, 5,6,7, 4,5,6,7};
__constant__ int c_I2[25] = {0,2,4,6, 1,3,5, 0,2,4,6, 1,3,5, 0,2,4,6, 1,3,5, 0,2,4,6};

// Scratch (device globals: no allocation allowed in kernel_launch)
static const int B_  = 1024;
static const int KC_ = 640;     // 625 valid features padded to 640
__device__ float g_X  [B_ * KC_];      // compact correlation features [B][640]
__device__ float g_W1g[1024 * KC_];    // gathered W1 columns, [n][640] (Bt layout)
__device__ float g_H1 [B_ * 1024];
__device__ float g_H2 [B_ * 1024];

// ---------------------------------------------------------------------------
// Correlation: one CTA per RoI. Both 256x49 patches in SMEM (row stride 50).
// 625 threads each compute one length-256 dot product.
// ---------------------------------------------------------------------------
__global__ __launch_bounds__(640) void corr_kernel(
    const float* __restrict__ p1, const float* __restrict__ p2,
    float* __restrict__ X)
{
    extern __shared__ float sm[];
    float* s1 = sm;            // [256][50]
    float* s2 = sm + 256 * 50; // [256][50]

    const int b = blockIdx.x;
    const int t = threadIdx.x;
    const float* g1 = p1 + b * 12544;
    const float* g2 = p2 + b * 12544;

    for (int idx = t; idx < 12544; idx += 640) {
        int c   = idx / 49;
        int pix = idx - c * 49;
        s1[c * 50 + pix] = g1[idx];
        s2[c * 50 + pix] = g2[idx];
    }
    __syncthreads();

    if (t < 625) {
        int u = t / 25;
        int v = t - u * 25;
        int pA = c_I [u] * 7 + c_I [v];
        int pB = c_I2[u] * 7 + c_I2[v];
        const float* a  = s1 + pA;
        const float* bb = s2 + pB;
        float acc = 0.f;
        #pragma unroll 8
        for (int c = 0; c < 256; c++)
            acc = fmaf(a[c * 50], bb[c * 50], acc);
        X[b * KC_ + t] = acc;
    } else {
        X[b * KC_ + t] = 0.f;   // zero-pad so GEMM can run K=640 uniformly
    }
}

// ---------------------------------------------------------------------------
// Gather only the 625 used W1 columns into [n][640] (row-major over n), with
// zero padding, so FC1 reads weights in native Bt layout.
// ---------------------------------------------------------------------------
__global__ __launch_bounds__(640) void gather_w1_kernel(
    const float* __restrict__ W1, float* __restrict__ W1g)
{
    const int n = blockIdx.x;
    const int k = threadIdx.x;
    float v_out = 0.f;
    if (k < 625) {
        int u = k / 25;
        int v = k - u * 25;
        int feat = (c_PH[u] * 16 + c_PH[v]) * 49 + c_I[u] * 7 + c_I[v];
        v_out = W1[n * 12544 + feat];
    }
    W1g[n * KC_ + k] = v_out;
}

// ---------------------------------------------------------------------------
// fp32 SIMT GEMM: C[M,N] = A[M,K] * Bt[N,K]^T + bias, optional relu.
// BM=BN=64, BK=16, 256 threads, 4x4 register microtiles.
// Bt is the native torch weight layout [out_features][in_features].
// ---------------------------------------------------------------------------
template<int RELU>
__global__ __launch_bounds__(256) void gemm_bias_kernel(
    const float* __restrict__ A, const float* __restrict__ Bt,
    const float* __restrict__ bias, float* __restrict__ C,
    int M, int N, int K)
{
    __shared__ float As[64][17];   // [m][k], padded stride 17 (conflict-free a reads)
    __shared__ float Bs[16][68];   // [k][n], padded stride 68 (16B-aligned rows)

    const int tid = threadIdx.x;
    const int m0 = blockIdx.y * 64;
    const int n0 = blockIdx.x * 64;
    const int lr = tid >> 2;          // 0..63
    const int lc = (tid & 3) * 4;     // 0,4,8,12
    const int ty = tid >> 4;          // 0..15 -> rows ty*4..ty*4+3
    const int tx = tid & 15;          // 0..15 -> cols tx*4..tx*4+3

    float acc[4][4];
    #pragma unroll
    for (int r = 0; r < 4; r++)
        #pragma unroll
        for (int c = 0; c < 4; c++) acc[r][c] = 0.f;

    for (int kb = 0; kb < K; kb += 16) {
        float4 av = *(const float4*)&A [(m0 + lr) * K + kb + lc];
        float4 bv = *(const float4*)&Bt[(n0 + lr) * K + kb + lc];
        As[lr][lc + 0] = av.x; As[lr][lc + 1] = av.y;
        As[lr][lc + 2] = av.z; As[lr][lc + 3] = av.w;
        Bs[lc + 0][lr] = bv.x; Bs[lc + 1][lr] = bv.y;
        Bs[lc + 2][lr] = bv.z; Bs[lc + 3][lr] = bv.w;
        __syncthreads();

        #pragma unroll
        for (int k = 0; k < 16; k++) {
            float a0 = As[ty * 4 + 0][k];
            float a1 = As[ty * 4 + 1][k];
            float a2 = As[ty * 4 + 2][k];
            float a3 = As[ty * 4 + 3][k];
            float4 b4 = *(const float4*)&Bs[k][tx * 4];
            acc[0][0] = fmaf(a0, b4.x, acc[0][0]);
            acc[0][1] = fmaf(a0, b4.y, acc[0][1]);
            acc[0][2] = fmaf(a0, b4.z, acc[0][2]);
            acc[0][3] = fmaf(a0, b4.w, acc[0][3]);
            acc[1][0] = fmaf(a1, b4.x, acc[1][0]);
            acc[1][1] = fmaf(a1, b4.y, acc[1][1]);
            acc[1][2] = fmaf(a1, b4.z, acc[1][2]);
            acc[1][3] = fmaf(a1, b4.w, acc[1][3]);
            acc[2][0] = fmaf(a2, b4.x, acc[2][0]);
            acc[2][1] = fmaf(a2, b4.y, acc[2][1]);
            acc[2][2] = fmaf(a2, b4.z, acc[2][2]);
            acc[2][3] = fmaf(a2, b4.w, acc[2][3]);
            acc[3][0] = fmaf(a3, b4.x, acc[3][0]);
            acc[3][1] = fmaf(a3, b4.y, acc[3][1]);
            acc[3][2] = fmaf(a3, b4.z, acc[3][2]);
            acc[3][3] = fmaf(a3, b4.w, acc[3][3]);
        }
        __syncthreads();
    }

    float4 bz = *(const float4*)&bias[n0 + tx * 4];
    #pragma unroll
    for (int r = 0; r < 4; r++) {
        float4 o;
        o.x = acc[r][0] + bz.x;
        o.y = acc[r][1] + bz.y;
        o.z = acc[r][2] + bz.z;
        o.w = acc[r][3] + bz.w;
        if (RELU) {
            o.x = fmaxf(o.x, 0.f); o.y = fmaxf(o.y, 0.f);
            o.z = fmaxf(o.z, 0.f); o.w = fmaxf(o.w, 0.f);
        }
        *(float4*)&C[(m0 + ty * 4 + r) * N + n0 + tx * 4] = o;
    }
}

// ---------------------------------------------------------------------------
// FC3: out[b][o] = H2[b] . W3[o] + b3[o], o in [0,4). One block per b,
// one warp per output, lane-strided float4 dot + shfl reduce.
// ---------------------------------------------------------------------------
__global__ __launch_bounds__(128) void fc3_kernel(
    const float* __restrict__ H2, const float* __restrict__ W3,
    const float* __restrict__ b3, float* __restrict__ out)
{
    const int b = blockIdx.x;
    const int o = threadIdx.x >> 5;
    const int l = threadIdx.x & 31;
    const float4* h = (const float4*)(H2 + b * 1024);
    const float4* w = (const float4*)(W3 + o * 1024);
    float s = 0.f;
    #pragma unroll
    for (int i = 0; i < 8; i++) {
        float4 hv = h[i * 32 + l];
        float4 wv = w[i * 32 + l];
        s = fmaf(hv.x, wv.x, s);
        s = fmaf(hv.y, wv.y, s);
        s = fmaf(hv.z, wv.z, s);
        s = fmaf(hv.w, wv.w, s);
    }
    #pragma unroll
    for (int off = 16; off; off >>= 1)
        s += __shfl_xor_sync(0xFFFFFFFFu, s, off);
    if (l == 0) out[b * 4 + o] = s + b3[o];
}

// ---------------------------------------------------------------------------
extern "C" void kernel_launch(void* const* d_in, const int* in_sizes, int n_in,
                              void* d_out, int out_size)
{
    (void)in_sizes; (void)n_in; (void)out_size;
    const float* p1 = (const float*)d_in[0];
    const float* p2 = (const float*)d_in[1];
    const float* W1 = (const float*)d_in[2];
    const float* b1 = (const float*)d_in[3];
    const float* W2 = (const float*)d_in[4];
    const float* b2 = (const float*)d_in[5];
    const float* W3 = (const float*)d_in[6];
    const float* b3 = (const float*)d_in[7];
    float* out = (float*)d_out;

    float *X, *W1g, *H1, *H2;
    cudaGetSymbolAddress((void**)&X,   g_X);
    cudaGetSymbolAddress((void**)&W1g, g_W1g);
    cudaGetSymbolAddress((void**)&H1,  g_H1);
    cudaGetSymbolAddress((void**)&H2,  g_H2);

    const int corr_smem = 2 * 256 * 50 * (int)sizeof(float);  // 102400 B
    cudaFuncSetAttribute(corr_kernel,
                         cudaFuncAttributeMaxDynamicSharedMemorySize, corr_smem);

    corr_kernel<<<1024, 640, corr_smem>>>(p1, p2, X);
    gather_w1_kernel<<<1024, 640>>>(W1, W1g);

    dim3 grid(16, 16);
    gemm_bias_kernel<1><<<grid, 256>>>(X,  W1g, b1, H1, 1024, 1024, 640);
    gemm_bias_kernel<1><<<grid, 256>>>(H1, W2,  b2, H2, 1024, 1024, 1024);
    fc3_kernel<<<1024, 128>>>(H2, W3, b3, out);
}